// round 2
// baseline (speedup 1.0000x reference)
#include <cuda_runtime.h>
#include <cuda_bf16.h>

#define N_NODES 100000
#define IN_FEATS 128
#define HMAX 256

// Scratch (allocation-free rule: __device__ globals)
__device__ float g_h1[(size_t)N_NODES * HMAX];
__device__ float g_h2[(size_t)N_NODES * HMAX];
__device__ float g_hN[(size_t)N_NODES * HMAX];
__device__ int   g_deg[N_NODES];
__device__ float g_invd[N_NODES];

__global__ void zero_f4_kernel(float4* __restrict__ p, int n4) {
    int i = blockIdx.x * blockDim.x + threadIdx.x;
    if (i < n4) p[i] = make_float4(0.f, 0.f, 0.f, 0.f);
}

__global__ void zero_int_kernel(int* __restrict__ p, int n) {
    int i = blockIdx.x * blockDim.x + threadIdx.x;
    if (i < n) p[i] = 0;
}

__global__ void deg_kernel(const int* __restrict__ dst, int E) {
    int i = blockIdx.x * blockDim.x + threadIdx.x;
    if (i < E) atomicAdd(&g_deg[dst[i]], 1);
}

__global__ void invd_kernel(int n) {
    int i = blockIdx.x * blockDim.x + threadIdx.x;
    if (i < n) g_invd[i] = 1.0f / fmaxf((float)g_deg[i], 1.0f);
}

// Warp per edge: lanes sweep the feature row with float4 loads, scalar atomic adds
// (consecutive lanes hit consecutive addresses -> RED wavefronts coalesce).
__global__ void agg_kernel(const float* __restrict__ h,
                           const int* __restrict__ src,
                           const int* __restrict__ dst,
                           float* __restrict__ hN,
                           int E, int d) {
    int gw   = (blockIdx.x * blockDim.x + threadIdx.x) >> 5;
    int lane = threadIdx.x & 31;
    if (gw >= E) return;
    int s = src[gw];
    int t = dst[gw];
    const float4* srow = (const float4*)(h + (size_t)s * d);
    float*        trow = hN + (size_t)t * d;
    int nvec = d >> 2;
    #pragma unroll 2
    for (int i = lane; i < nvec; i += 32) {
        float4 v = srow[i];
        float* p = trow + i * 4;
        atomicAdd(p + 0, v.x);
        atomicAdd(p + 1, v.y);
        atomicAdd(p + 2, v.z);
        atomicAdd(p + 3, v.w);
    }
}

// out[m][n] = sum_k A[m][k] * W[n][k] + bias[n], A = [A0 | A1*invd], K = 2d.
// BM=128, BN=64, BK=16, 256 threads, each thread computes 8x4.
#define BM 128
#define BN 64
#define BK 16
#define TM 8
#define TN 4

__global__ __launch_bounds__(256)
void gemm_concat_kernel(const float* __restrict__ A0,
                        const float* __restrict__ A1,
                        const float* __restrict__ invd,
                        const float* __restrict__ W,
                        const float* __restrict__ bias,
                        float* __restrict__ out,
                        int M, int d, int Nout, int do_relu) {
    __shared__ float As[BK][BM + 4];
    __shared__ float Bs[BK][BN];

    const int K = 2 * d;
    const int bm = blockIdx.y * BM;
    const int bn = blockIdx.x * BN;
    const int tid = threadIdx.x;
    const int tx = tid & 15;   // 16 col groups of TN=4
    const int ty = tid >> 4;   // 16 row groups of TM=8

    float acc[TM][TN];
    #pragma unroll
    for (int i = 0; i < TM; i++)
        #pragma unroll
        for (int j = 0; j < TN; j++)
            acc[i][j] = 0.f;

    for (int k0 = 0; k0 < K; k0 += BK) {
        // A tile: BM x BK = 2048 elems, 8 per thread; idx = i*256 + tid keeps
        // consecutive tids on consecutive k within a row (coalesced).
        #pragma unroll
        for (int i = 0; i < 8; i++) {
            int idx = i * 256 + tid;
            int m  = idx >> 4;       // /BK
            int kk = idx & 15;       // %BK
            int gm = bm + m;
            int gk = k0 + kk;
            float v = 0.f;
            if (gm < M) {
                if (gk < d) v = A0[(size_t)gm * d + gk];
                else        v = A1[(size_t)gm * d + (gk - d)] * invd[gm];
            }
            As[kk][m] = v;
        }
        // B tile: BN x BK = 1024 elems, 4 per thread
        #pragma unroll
        for (int i = 0; i < 4; i++) {
            int idx = i * 256 + tid;
            int n  = idx >> 4;
            int kk = idx & 15;
            Bs[kk][n] = W[(size_t)(bn + n) * K + (k0 + kk)];
        }
        __syncthreads();

        #pragma unroll
        for (int kk = 0; kk < BK; kk++) {
            float a[TM], b[TN];
            #pragma unroll
            for (int i = 0; i < TM; i++) a[i] = As[kk][ty * TM + i];
            #pragma unroll
            for (int j = 0; j < TN; j++) b[j] = Bs[kk][tx * TN + j];
            #pragma unroll
            for (int i = 0; i < TM; i++)
                #pragma unroll
                for (int j = 0; j < TN; j++)
                    acc[i][j] += a[i] * b[j];
        }
        __syncthreads();
    }

    #pragma unroll
    for (int i = 0; i < TM; i++) {
        int gm = bm + ty * TM + i;
        if (gm >= M) continue;
        #pragma unroll
        for (int j = 0; j < TN; j++) {
            int gn = bn + tx * TN + j;
            float v = acc[i][j] + bias[gn];
            if (do_relu) v = fmaxf(v, 0.f);
            out[(size_t)gm * Nout + gn] = v;
        }
    }
}

extern "C" void kernel_launch(void* const* d_in, const int* in_sizes, int n_in,
                              void* d_out, int out_size) {
    const float* x  = (const float*)d_in[0];
    const int*   src = (const int*)d_in[1];
    const int*   dst = (const int*)d_in[2];
    const float* W1 = (const float*)d_in[3];
    const float* b1 = (const float*)d_in[4];
    const float* W2 = (const float*)d_in[5];
    const float* b2 = (const float*)d_in[6];
    const float* W3 = (const float*)d_in[7];
    const float* b3 = (const float*)d_in[8];
    float* out = (float*)d_out;

    const int E = in_sizes[1];
    const int M = in_sizes[0] / IN_FEATS;   // 100000

    float *h1, *h2, *hN, *invd;
    int* deg;
    cudaGetSymbolAddress((void**)&h1,   g_h1);
    cudaGetSymbolAddress((void**)&h2,   g_h2);
    cudaGetSymbolAddress((void**)&hN,   g_hN);
    cudaGetSymbolAddress((void**)&deg,  g_deg);
    cudaGetSymbolAddress((void**)&invd, g_invd);

    const int T = 256;
    // degrees (recomputed every call: deterministic, no caching)
    zero_int_kernel<<<(M + T - 1) / T, T>>>(deg, M);
    deg_kernel<<<(E + T - 1) / T, T>>>(dst, E);
    invd_kernel<<<(M + T - 1) / T, T>>>(M);

    // ---- Layer 1: d=128, Nout=256, relu ----
    {
        int d = IN_FEATS;
        int n4 = (M * d) / 4;
        zero_f4_kernel<<<(n4 + T - 1) / T, T>>>((float4*)hN, n4);
        agg_kernel<<<(E * 32 + T - 1) / T, T>>>(x, src, dst, hN, E, d);
        dim3 grid(256 / BN, (M + BM - 1) / BM);
        gemm_concat_kernel<<<grid, 256>>>(x, hN, invd, W1, b1, h1, M, d, 256, 1);
    }
    // ---- Layer 2: d=256, Nout=256, relu ----
    {
        int d = 256;
        int n4 = (M * d) / 4;
        zero_f4_kernel<<<(n4 + T - 1) / T, T>>>((float4*)hN, n4);
        agg_kernel<<<(E * 32 + T - 1) / T, T>>>(h1, src, dst, hN, E, d);
        dim3 grid(256 / BN, (M + BM - 1) / BM);
        gemm_concat_kernel<<<grid, 256>>>(h1, hN, invd, W2, b2, h2, M, d, 256, 1);
    }
    // ---- Layer 3: d=256, Nout=64, no relu ----
    {
        int d = 256;
        int n4 = (M * d) / 4;
        zero_f4_kernel<<<(n4 + T - 1) / T, T>>>((float4*)hN, n4);
        agg_kernel<<<(E * 32 + T - 1) / T, T>>>(h2, src, dst, hN, E, d);
        dim3 grid(64 / BN, (M + BM - 1) / BM);
        gemm_concat_kernel<<<grid, 256>>>(h2, hN, invd, W3, b3, out, M, d, 64, 0);
    }
}

// round 6
// speedup vs baseline: 2.6699x; 2.6699x over previous
#include <cuda_runtime.h>
#include <cuda_bf16.h>

#define N_NODES 100000
#define N_EDGES_MAX 1600000
#define IN_FEATS 128
#define HMAX 256

// Scratch (allocation-free rule: __device__ globals)
__device__ float g_h1[(size_t)N_NODES * HMAX];
__device__ float g_h2[(size_t)N_NODES * HMAX];
__device__ float g_hN[(size_t)N_NODES * HMAX];
__device__ int   g_deg[N_NODES];
__device__ float g_invd[N_NODES];
__device__ int   g_rowptr[N_NODES + 1];
__device__ int   g_pos[N_NODES];
__device__ int   g_csr[N_EDGES_MAX];
__device__ int   g_bsum[128];

// ---------------- degree / inverse degree ----------------
__global__ void zero_int_kernel(int* __restrict__ p, int n) {
    int i = blockIdx.x * blockDim.x + threadIdx.x;
    if (i < n) p[i] = 0;
}

__global__ void deg_kernel(const int* __restrict__ dst, int E) {
    int i = blockIdx.x * blockDim.x + threadIdx.x;
    if (i < E) atomicAdd(&g_deg[dst[i]], 1);
}

__global__ void invd_kernel(int n) {
    int i = blockIdx.x * blockDim.x + threadIdx.x;
    if (i < n) g_invd[i] = 1.0f / fmaxf((float)g_deg[i], 1.0f);
}

// ---------------- prefix sum (CSR rowptr) ----------------
#define SCAN_T 1024

__global__ void scan1_kernel(int* __restrict__ excl, int n) {
    __shared__ int s[SCAN_T];
    int i = blockIdx.x * SCAN_T + threadIdx.x;
    int v = (i < n) ? g_deg[i] : 0;
    s[threadIdx.x] = v;
    __syncthreads();
    for (int off = 1; off < SCAN_T; off <<= 1) {
        int t = (threadIdx.x >= off) ? s[threadIdx.x - off] : 0;
        __syncthreads();
        s[threadIdx.x] += t;
        __syncthreads();
    }
    if (i < n) excl[i] = s[threadIdx.x] - v;
    if (threadIdx.x == SCAN_T - 1) g_bsum[blockIdx.x] = s[SCAN_T - 1];
}

__global__ void scan2_kernel(int nb) {
    __shared__ int s[128];
    int v = (threadIdx.x < nb) ? g_bsum[threadIdx.x] : 0;
    s[threadIdx.x] = v;
    __syncthreads();
    for (int off = 1; off < 128; off <<= 1) {
        int t = (threadIdx.x >= off) ? s[threadIdx.x - off] : 0;
        __syncthreads();
        s[threadIdx.x] += t;
        __syncthreads();
    }
    if (threadIdx.x < nb) g_bsum[threadIdx.x] = s[threadIdx.x] - v;  // exclusive
}

__global__ void scan3_kernel(int n, int E) {
    int i = blockIdx.x * blockDim.x + threadIdx.x;
    if (i < n) {
        int r = g_rowptr[i] + g_bsum[i / SCAN_T];
        g_rowptr[i] = r;
        g_pos[i] = r;
    }
    if (i == 0) g_rowptr[n] = E;
}

__global__ void scatter_kernel(const int* __restrict__ src,
                               const int* __restrict__ dst, int E) {
    int i = blockIdx.x * blockDim.x + threadIdx.x;
    if (i < E) {
        int t = dst[i];
        int slot = atomicAdd(&g_pos[t], 1);
        g_csr[slot] = src[i];
    }
}

// ---------------- pull-style mean aggregation ----------------
// One block per dst node, blockDim = d (feature per thread).
// hN[node] = mean over neighbors of h[src] (0 for isolated nodes).
__global__ __launch_bounds__(HMAX)
void agg_csr_kernel(const float* __restrict__ h, float* __restrict__ hN, int d) {
    int node = blockIdx.x;
    int tid = threadIdx.x;
    int start = g_rowptr[node];
    int end   = g_rowptr[node + 1];
    __shared__ int sidx[128];
    float acc = 0.f;
    for (int base = start; base < end; base += 128) {
        int n = min(128, end - base);
        if (tid < n) sidx[tid] = g_csr[base + tid];
        __syncthreads();
        int j = 0;
        for (; j + 4 <= n; j += 4) {
            const float* r0 = h + (size_t)sidx[j + 0] * d;
            const float* r1 = h + (size_t)sidx[j + 1] * d;
            const float* r2 = h + (size_t)sidx[j + 2] * d;
            const float* r3 = h + (size_t)sidx[j + 3] * d;
            acc += r0[tid];
            acc += r1[tid];
            acc += r2[tid];
            acc += r3[tid];
        }
        for (; j < n; j++) acc += h[(size_t)g_csr[base + j] * d + tid];
        __syncthreads();
    }
    hN[(size_t)node * d + tid] = acc * g_invd[node];
}

// ---------------- SGEMM with concat input ----------------
// out[m][n] = sum_k A[m][k] * W[n][k] + bias[n],  A = [A0 | A1],  K = 2d.
// BM=128, BK=8, 256 threads, thread tile TM=8 x TN=BN/16.
template <int BN>
__global__ __launch_bounds__(256)
void gemm_concat_kernel(const float* __restrict__ A0,
                        const float* __restrict__ A1,
                        const float* __restrict__ W,
                        const float* __restrict__ bias,
                        float* __restrict__ out,
                        int M, int d, int Nout, int do_relu) {
    constexpr int BM = 128;
    constexpr int BK = 8;
    constexpr int TM = 8;
    constexpr int TN = BN / 16;

    __shared__ __align__(16) float As[BK][BM + 4];
    __shared__ __align__(16) float Bs[BK][BN + 4];

    const int K = 2 * d;
    const int bm = blockIdx.x * BM;
    const int bn = blockIdx.y * BN;
    const int tid = threadIdx.x;
    const int tx = tid & 15;
    const int ty = tid >> 4;

    float acc[TM][TN];
    #pragma unroll
    for (int i = 0; i < TM; i++)
        #pragma unroll
        for (int j = 0; j < TN; j++) acc[i][j] = 0.f;

    const int arow = tid >> 1;
    const int akc  = (tid & 1) * 4;

    for (int k0 = 0; k0 < K; k0 += BK) {
        // ---- A tile: 128 rows x 8 k, one float4 per thread, transposed ----
        {
            int gm = bm + arow;
            int gk = k0 + akc;
            float4 av = make_float4(0.f, 0.f, 0.f, 0.f);
            if (gm < M) {
                const float* base = (gk < d) ? (A0 + (size_t)gm * d + gk)
                                             : (A1 + (size_t)gm * d + (gk - d));
                av = *(const float4*)base;
            }
            As[akc + 0][arow] = av.x;
            As[akc + 1][arow] = av.y;
            As[akc + 2][arow] = av.z;
            As[akc + 3][arow] = av.w;
        }
        // ---- B tile: BN rows x 8 k, transposed ----
        if (BN == 128) {
            int brow = tid >> 1;
            int bkc  = (tid & 1) * 4;
            float4 bv = *(const float4*)(W + (size_t)(bn + brow) * K + k0 + bkc);
            Bs[bkc + 0][brow] = bv.x;
            Bs[bkc + 1][brow] = bv.y;
            Bs[bkc + 2][brow] = bv.z;
            Bs[bkc + 3][brow] = bv.w;
        } else {  // BN == 64
            int brow = tid >> 2;
            int bkc  = (tid & 3) * 2;
            float2 bv = *(const float2*)(W + (size_t)(bn + brow) * K + k0 + bkc);
            Bs[bkc + 0][brow] = bv.x;
            Bs[bkc + 1][brow] = bv.y;
        }
        __syncthreads();

        #pragma unroll
        for (int kk = 0; kk < BK; kk++) {
            float a[TM], b[TN];
            float4 a0 = *(const float4*)&As[kk][ty * TM];
            float4 a1 = *(const float4*)&As[kk][ty * TM + 4];
            a[0] = a0.x; a[1] = a0.y; a[2] = a0.z; a[3] = a0.w;
            a[4] = a1.x; a[5] = a1.y; a[6] = a1.z; a[7] = a1.w;
            float4 b0 = *(const float4*)&Bs[kk][tx * TN];
            b[0] = b0.x; b[1] = b0.y; b[2] = b0.z; b[3] = b0.w;
            if (TN == 8) {
                float4 b1 = *(const float4*)&Bs[kk][tx * TN + 4];
                b[4] = b1.x; b[5] = b1.y; b[6] = b1.z; b[7] = b1.w;
            }
            #pragma unroll
            for (int i = 0; i < TM; i++)
                #pragma unroll
                for (int j = 0; j < TN; j++)
                    acc[i][j] += a[i] * b[j];
        }
        __syncthreads();
    }

    // ---- epilogue: bias (+ relu), vectorized stores ----
    #pragma unroll
    for (int i = 0; i < TM; i++) {
        int gm = bm + ty * TM + i;
        if (gm >= M) continue;
        #pragma unroll
        for (int j4 = 0; j4 < TN; j4 += 4) {
            int gn = bn + tx * TN + j4;
            float4 v;
            v.x = acc[i][j4 + 0] + bias[gn + 0];
            v.y = acc[i][j4 + 1] + bias[gn + 1];
            v.z = acc[i][j4 + 2] + bias[gn + 2];
            v.w = acc[i][j4 + 3] + bias[gn + 3];
            if (do_relu) {
                v.x = fmaxf(v.x, 0.f); v.y = fmaxf(v.y, 0.f);
                v.z = fmaxf(v.z, 0.f); v.w = fmaxf(v.w, 0.f);
            }
            *(float4*)(out + (size_t)gm * Nout + gn) = v;
        }
    }
}

extern "C" void kernel_launch(void* const* d_in, const int* in_sizes, int n_in,
                              void* d_out, int out_size) {
    const float* x   = (const float*)d_in[0];
    const int*   src = (const int*)d_in[1];
    const int*   dst = (const int*)d_in[2];
    const float* W1 = (const float*)d_in[3];
    const float* b1 = (const float*)d_in[4];
    const float* W2 = (const float*)d_in[5];
    const float* b2 = (const float*)d_in[6];
    const float* W3 = (const float*)d_in[7];
    const float* b3 = (const float*)d_in[8];
    float* out = (float*)d_out;

    const int E = in_sizes[1];
    const int M = in_sizes[0] / IN_FEATS;   // 100000

    float *h1, *h2, *hN;
    int *deg, *rowptr;
    cudaGetSymbolAddress((void**)&h1,     g_h1);
    cudaGetSymbolAddress((void**)&h2,     g_h2);
    cudaGetSymbolAddress((void**)&hN,     g_hN);
    cudaGetSymbolAddress((void**)&deg,    g_deg);
    cudaGetSymbolAddress((void**)&rowptr, g_rowptr);

    const int T = 256;

    // degrees + CSR build (recomputed every call: deterministic work)
    zero_int_kernel<<<(M + T - 1) / T, T>>>(deg, M);
    deg_kernel<<<(E + T - 1) / T, T>>>(dst, E);
    invd_kernel<<<(M + T - 1) / T, T>>>(M);

    int nb = (M + SCAN_T - 1) / SCAN_T;
    scan1_kernel<<<nb, SCAN_T>>>(rowptr, M);
    scan2_kernel<<<1, 128>>>(nb);
    scan3_kernel<<<(M + T - 1) / T, T>>>(M, E);
    scatter_kernel<<<(E + T - 1) / T, T>>>(src, dst, E);

    // ---- Layer 1: d=128, Nout=256, relu ----
    {
        int d = IN_FEATS;
        agg_csr_kernel<<<M, d>>>(x, hN, d);
        dim3 grid((M + 127) / 128, 256 / 128);
        gemm_concat_kernel<128><<<grid, 256>>>(x, hN, W1, b1, h1, M, d, 256, 1);
    }
    // ---- Layer 2: d=256, Nout=256, relu ----
    {
        int d = 256;
        agg_csr_kernel<<<M, d>>>(h1, hN, d);
        dim3 grid((M + 127) / 128, 256 / 128);
        gemm_concat_kernel<128><<<grid, 256>>>(h1, hN, W2, b2, h2, M, d, 256, 1);
    }
    // ---- Layer 3: d=256, Nout=64, no relu ----
    {
        int d = 256;
        agg_csr_kernel<<<M, d>>>(h2, hN, d);
        dim3 grid((M + 127) / 128, 64 / 64);
        gemm_concat_kernel<64><<<grid, 256>>>(h2, hN, W3, b3, out, M, d, 64, 0);
    }
}

// round 8
// speedup vs baseline: 3.6674x; 1.3736x over previous
#include <cuda_runtime.h>
#include <cuda_bf16.h>
#include <mma.h>
#include <cstdint>

using namespace nvcuda;

#define N_NODES 100000
#define N_EDGES_MAX 1600000
#define IN_FEATS 128
#define HMAX 256

// Scratch (allocation-free rule: __device__ globals)
__device__ float g_h1[(size_t)N_NODES * HMAX];
__device__ float g_h2[(size_t)N_NODES * HMAX];
__device__ float g_hN[(size_t)N_NODES * HMAX];
__device__ int   g_deg[N_NODES];
__device__ float g_invd[N_NODES];
__device__ int   g_rowptr[N_NODES + 1];
__device__ int   g_pos[N_NODES];
__device__ int   g_csr[N_EDGES_MAX];
__device__ int   g_bsum[128];

// ---------------- degree / inverse degree ----------------
__global__ void zero_int_kernel(int* __restrict__ p, int n) {
    int i = blockIdx.x * blockDim.x + threadIdx.x;
    if (i < n) p[i] = 0;
}

__global__ void deg_kernel(const int* __restrict__ dst, int E) {
    int i = blockIdx.x * blockDim.x + threadIdx.x;
    if (i < E) atomicAdd(&g_deg[dst[i]], 1);
}

__global__ void invd_kernel(int n) {
    int i = blockIdx.x * blockDim.x + threadIdx.x;
    if (i < n) g_invd[i] = 1.0f / fmaxf((float)g_deg[i], 1.0f);
}

// ---------------- prefix sum (CSR rowptr) ----------------
#define SCAN_T 1024

__global__ void scan1_kernel(int* __restrict__ excl, int n) {
    __shared__ int s[SCAN_T];
    int i = blockIdx.x * SCAN_T + threadIdx.x;
    int v = (i < n) ? g_deg[i] : 0;
    s[threadIdx.x] = v;
    __syncthreads();
    for (int off = 1; off < SCAN_T; off <<= 1) {
        int t = (threadIdx.x >= off) ? s[threadIdx.x - off] : 0;
        __syncthreads();
        s[threadIdx.x] += t;
        __syncthreads();
    }
    if (i < n) excl[i] = s[threadIdx.x] - v;
    if (threadIdx.x == SCAN_T - 1) g_bsum[blockIdx.x] = s[SCAN_T - 1];
}

__global__ void scan2_kernel(int nb) {
    __shared__ int s[128];
    int v = (threadIdx.x < nb) ? g_bsum[threadIdx.x] : 0;
    s[threadIdx.x] = v;
    __syncthreads();
    for (int off = 1; off < 128; off <<= 1) {
        int t = (threadIdx.x >= off) ? s[threadIdx.x - off] : 0;
        __syncthreads();
        s[threadIdx.x] += t;
        __syncthreads();
    }
    if (threadIdx.x < nb) g_bsum[threadIdx.x] = s[threadIdx.x] - v;  // exclusive
}

__global__ void scan3_kernel(int n, int E) {
    int i = blockIdx.x * blockDim.x + threadIdx.x;
    if (i < n) {
        int r = g_rowptr[i] + g_bsum[i / SCAN_T];
        g_rowptr[i] = r;
        g_pos[i] = r;
    }
    if (i == 0) g_rowptr[n] = E;
}

__global__ void scatter_kernel(const int* __restrict__ src,
                               const int* __restrict__ dst, int E) {
    int i = blockIdx.x * blockDim.x + threadIdx.x;
    if (i < E) {
        int t = dst[i];
        int slot = atomicAdd(&g_pos[t], 1);
        g_csr[slot] = src[i];
    }
}

// ---------------- pull-style mean aggregation ----------------
__global__ __launch_bounds__(HMAX)
void agg_csr_kernel(const float* __restrict__ h, float* __restrict__ hN, int d) {
    int node = blockIdx.x;
    int tid = threadIdx.x;
    int start = g_rowptr[node];
    int end   = g_rowptr[node + 1];
    __shared__ int sidx[128];
    float acc = 0.f;
    for (int base = start; base < end; base += 128) {
        int n = min(128, end - base);
        if (tid < n) sidx[tid] = g_csr[base + tid];
        __syncthreads();
        int j = 0;
        for (; j + 4 <= n; j += 4) {
            const float* r0 = h + (size_t)sidx[j + 0] * d;
            const float* r1 = h + (size_t)sidx[j + 1] * d;
            const float* r2 = h + (size_t)sidx[j + 2] * d;
            const float* r3 = h + (size_t)sidx[j + 3] * d;
            acc += r0[tid];
            acc += r1[tid];
            acc += r2[tid];
            acc += r3[tid];
        }
        for (; j < n; j++) acc += h[(size_t)g_csr[base + j] * d + tid];
        __syncthreads();
    }
    hN[(size_t)node * d + tid] = acc * g_invd[node];
}

// ================= bf16x2-split WMMA GEMM (HMMA, no 'a' features) =================
// out[m][n] = sum_k A[m][k]*W[n][k] + bias[n],  A = [A0 | A1], K = 2d.
// Split: v = hi + lo (bf16 each);  D += Ahi*Bhi + Ahi*Blo + Alo*Bhi (fp32 accum).
// CTA: BM=128 x BN, BK=32. 512 threads = 16 warps (4x4), warp tile 32 x BN/4.

__device__ __forceinline__ void split_store8(__nv_bfloat16* __restrict__ hi,
                                             __nv_bfloat16* __restrict__ lo,
                                             float4 v0, float4 v1) {
    float f[8] = {v0.x, v0.y, v0.z, v0.w, v1.x, v1.y, v1.z, v1.w};
    #pragma unroll
    for (int i = 0; i < 8; i++) {
        __nv_bfloat16 h = __float2bfloat16_rn(f[i]);
        __nv_bfloat16 l = __float2bfloat16_rn(f[i] - __bfloat162float(h));
        hi[i] = h;
        lo[i] = l;
    }
}

template <int BN>
__global__ __launch_bounds__(512)
void gemm_wmma_kernel(const float* __restrict__ A0,
                      const float* __restrict__ A1,
                      const float* __restrict__ W,
                      const float* __restrict__ bias,
                      float* __restrict__ out,
                      int M, int d, int Nout, int relu) {
    constexpr int BM  = 128;
    constexpr int BK  = 32;
    constexpr int LDT = 40;           // bf16 tile stride (pad; 80B, 16B-aligned frags)
    constexpr int WN  = BN / 4;       // warp N tile: 32 or 16
    constexpr int FN  = WN / 16;      // 2 or 1
    constexpr int LDC = BN + 4;       // f32 epilogue stride

    extern __shared__ char smraw[];
    __nv_bfloat16* aHi = (__nv_bfloat16*)smraw;
    __nv_bfloat16* aLo = aHi + BM * LDT;
    __nv_bfloat16* bHi = aLo + BM * LDT;
    __nv_bfloat16* bLo = bHi + BN * LDT;
    float* Cs = (float*)smraw;        // epilogue reuse (after sync)

    const int tid = threadIdx.x;
    const int wid = tid >> 5;
    const int m0 = (wid >> 2) * 32;
    const int n0 = (wid & 3) * WN;
    const int bm = blockIdx.x * BM;
    const int bn = blockIdx.y * BN;
    const int K = 2 * d;
    const int nsteps = K / BK;

    wmma::fragment<wmma::accumulator, 16, 16, 16, float> acc[2][FN];
    #pragma unroll
    for (int fm = 0; fm < 2; fm++)
        #pragma unroll
        for (int fn = 0; fn < FN; fn++)
            wmma::fill_fragment(acc[fm][fn], 0.f);

    // staging geometry
    const int ar = tid >> 2;                 // A: 128 rows, 4 thr/row, 8 cols
    const int ac = (tid & 3) * 8;
    const int br = (BN == 128) ? (tid >> 2) : (tid >> 3);
    const int bc = (BN == 128) ? (tid & 3) * 8 : (tid & 7) * 4;
    constexpr int NB4 = (BN == 128) ? 2 : 1; // B float4s per thread

    float4 ra[2], rb[2];

    auto loadA = [&](int k0) {
        int gm = bm + ar;
        if (gm < M) {
            const float* p = (k0 < d) ? (A0 + (size_t)gm * d + k0 + ac)
                                      : (A1 + (size_t)gm * d + (k0 - d) + ac);
            ra[0] = *(const float4*)(p);
            ra[1] = *(const float4*)(p + 4);
        } else {
            ra[0] = ra[1] = make_float4(0.f, 0.f, 0.f, 0.f);
        }
    };
    auto loadB = [&](int k0) {
        const float* p = W + (size_t)(bn + br) * K + k0 + bc;
        rb[0] = *(const float4*)(p);
        if (NB4 == 2) rb[1] = *(const float4*)(p + 4);
    };

    loadA(0);
    loadB(0);

    for (int s = 0; s < nsteps; s++) {
        __syncthreads();  // previous compute done before smem overwrite
        split_store8(aHi + ar * LDT + ac, aLo + ar * LDT + ac, ra[0], ra[1]);
        if (NB4 == 2) {
            split_store8(bHi + br * LDT + bc, bLo + br * LDT + bc, rb[0], rb[1]);
        } else {
            float f[4] = {rb[0].x, rb[0].y, rb[0].z, rb[0].w};
            #pragma unroll
            for (int i = 0; i < 4; i++) {
                __nv_bfloat16 h = __float2bfloat16_rn(f[i]);
                __nv_bfloat16 l = __float2bfloat16_rn(f[i] - __bfloat162float(h));
                bHi[br * LDT + bc + i] = h;
                bLo[br * LDT + bc + i] = l;
            }
        }
        __syncthreads();

        if (s + 1 < nsteps) {  // prefetch next step; overlaps HMMA below
            loadA((s + 1) * BK);
            loadB((s + 1) * BK);
        }

        #pragma unroll
        for (int ks = 0; ks < BK; ks += 16) {
            wmma::fragment<wmma::matrix_a, 16, 16, 16, __nv_bfloat16, wmma::row_major> a_hi[2], a_lo[2];
            #pragma unroll
            for (int fm = 0; fm < 2; fm++) {
                wmma::load_matrix_sync(a_hi[fm], aHi + (m0 + fm * 16) * LDT + ks, LDT);
                wmma::load_matrix_sync(a_lo[fm], aLo + (m0 + fm * 16) * LDT + ks, LDT);
            }
            #pragma unroll
            for (int fn = 0; fn < FN; fn++) {
                wmma::fragment<wmma::matrix_b, 16, 16, 16, __nv_bfloat16, wmma::col_major> b_hi, b_lo;
                wmma::load_matrix_sync(b_hi, bHi + (n0 + fn * 16) * LDT + ks, LDT);
                wmma::load_matrix_sync(b_lo, bLo + (n0 + fn * 16) * LDT + ks, LDT);
                #pragma unroll
                for (int fm = 0; fm < 2; fm++) {
                    wmma::mma_sync(acc[fm][fn], a_hi[fm], b_hi, acc[fm][fn]);
                    wmma::mma_sync(acc[fm][fn], a_hi[fm], b_lo, acc[fm][fn]);
                    wmma::mma_sync(acc[fm][fn], a_lo[fm], b_hi, acc[fm][fn]);
                }
            }
        }
    }

    // ---- epilogue: frags -> smem -> bias/relu -> global ----
    __syncthreads();
    #pragma unroll
    for (int fm = 0; fm < 2; fm++)
        #pragma unroll
        for (int fn = 0; fn < FN; fn++)
            wmma::store_matrix_sync(Cs + (m0 + fm * 16) * LDC + n0 + fn * 16,
                                    acc[fm][fn], LDC, wmma::mem_row_major);
    __syncthreads();

    {
        constexpr int CPT = (BM * BN) / 512;     // floats per thread: 32 or 16
        constexpr int NF4 = CPT / 4;             // 8 or 4
        const int row = tid >> 2;
        const int c0 = (tid & 3) * CPT;
        const int gm = bm + row;
        if (gm < M) {
            #pragma unroll
            for (int j = 0; j < NF4; j++) {
                int c = c0 + j * 4;
                float4 v = *(const float4*)(Cs + row * LDC + c);
                v.x += bias[bn + c + 0];
                v.y += bias[bn + c + 1];
                v.z += bias[bn + c + 2];
                v.w += bias[bn + c + 3];
                if (relu) {
                    v.x = fmaxf(v.x, 0.f); v.y = fmaxf(v.y, 0.f);
                    v.z = fmaxf(v.z, 0.f); v.w = fmaxf(v.w, 0.f);
                }
                *(float4*)(out + (size_t)gm * Nout + bn + c) = v;
            }
        }
    }
}

extern "C" void kernel_launch(void* const* d_in, const int* in_sizes, int n_in,
                              void* d_out, int out_size) {
    const float* x   = (const float*)d_in[0];
    const int*   src = (const int*)d_in[1];
    const int*   dst = (const int*)d_in[2];
    const float* W1 = (const float*)d_in[3];
    const float* b1 = (const float*)d_in[4];
    const float* W2 = (const float*)d_in[5];
    const float* b2 = (const float*)d_in[6];
    const float* W3 = (const float*)d_in[7];
    const float* b3 = (const float*)d_in[8];
    float* out = (float*)d_out;

    const int E = in_sizes[1];
    const int M = in_sizes[0] / IN_FEATS;   // 100000

    float *h1, *h2, *hN;
    int *deg, *rowptr;
    cudaGetSymbolAddress((void**)&h1,     g_h1);
    cudaGetSymbolAddress((void**)&h2,     g_h2);
    cudaGetSymbolAddress((void**)&hN,     g_hN);
    cudaGetSymbolAddress((void**)&deg,    g_deg);
    cudaGetSymbolAddress((void**)&rowptr, g_rowptr);

    // dynamic smem: max(tiles, epilogue Cs)
    const int SMEM128 = 128 * 132 * 4;  // 67584 (Cs dominates 40960 tiles)
    const int SMEM64  = 128 * 68 * 4;   // 34816 (tiles 30720)
    cudaFuncSetAttribute(gemm_wmma_kernel<128>,
                         cudaFuncAttributeMaxDynamicSharedMemorySize, SMEM128);
    cudaFuncSetAttribute(gemm_wmma_kernel<64>,
                         cudaFuncAttributeMaxDynamicSharedMemorySize, SMEM64);

    const int T = 256;
    const int gx = (M + 127) / 128;

    // degrees + CSR build (recomputed every call: deterministic work)
    zero_int_kernel<<<(M + T - 1) / T, T>>>(deg, M);
    deg_kernel<<<(E + T - 1) / T, T>>>(dst, E);
    invd_kernel<<<(M + T - 1) / T, T>>>(M);

    int nb = (M + SCAN_T - 1) / SCAN_T;
    scan1_kernel<<<nb, SCAN_T>>>(rowptr, M);
    scan2_kernel<<<1, 128>>>(nb);
    scan3_kernel<<<(M + T - 1) / T, T>>>(M, E);
    scatter_kernel<<<(E + T - 1) / T, T>>>(src, dst, E);

    // ---- Layer 1: d=128, Nout=256, relu ----
    agg_csr_kernel<<<M, IN_FEATS>>>(x, hN, IN_FEATS);
    gemm_wmma_kernel<128><<<dim3(gx, 2), 512, SMEM128>>>(x, hN, W1, b1, h1, M, IN_FEATS, 256, 1);

    // ---- Layer 2: d=256, Nout=256, relu ----
    agg_csr_kernel<<<M, 256>>>(h1, hN, 256);
    gemm_wmma_kernel<128><<<dim3(gx, 2), 512, SMEM128>>>(h1, hN, W2, b2, h2, M, 256, 256, 1);

    // ---- Layer 3: d=256, Nout=64, no relu ----
    agg_csr_kernel<<<M, 256>>>(h2, hN, 256);
    gemm_wmma_kernel<64><<<dim3(gx, 1), 512, SMEM64>>>(h2, hN, W3, b3, out, M, 256, 64, 0);
}

// round 10
// speedup vs baseline: 4.2576x; 1.1609x over previous
#include <cuda_runtime.h>
#include <cuda_bf16.h>
#include <mma.h>
#include <cstdint>

using namespace nvcuda;

#define N_NODES 100000
#define N_EDGES_MAX 1600000
#define IN_FEATS 128
#define HMAX 256

// Scratch (allocation-free rule: __device__ globals)
__device__ float g_h1[(size_t)N_NODES * HMAX];
__device__ float g_h2[(size_t)N_NODES * HMAX];
__device__ float g_hN[(size_t)N_NODES * HMAX];
__device__ int   g_deg[N_NODES];
__device__ float g_invd[N_NODES];
__device__ int   g_rowptr[N_NODES + 1];
__device__ int   g_pos[N_NODES];
__device__ int   g_csr[N_EDGES_MAX];
__device__ int   g_bsum[128];

// ---------------- degree / inverse degree ----------------
__global__ void zero_int_kernel(int* __restrict__ p, int n) {
    int i = blockIdx.x * blockDim.x + threadIdx.x;
    if (i < n) p[i] = 0;
}

__global__ void deg_kernel(const int* __restrict__ dst, int E) {
    int i = blockIdx.x * blockDim.x + threadIdx.x;
    if (i < E) atomicAdd(&g_deg[dst[i]], 1);
}

__global__ void invd_kernel(int n) {
    int i = blockIdx.x * blockDim.x + threadIdx.x;
    if (i < n) g_invd[i] = 1.0f / fmaxf((float)g_deg[i], 1.0f);
}

// ---------------- prefix sum (CSR rowptr) ----------------
#define SCAN_T 1024

__global__ void scan1_kernel(int* __restrict__ excl, int n) {
    __shared__ int s[SCAN_T];
    int i = blockIdx.x * SCAN_T + threadIdx.x;
    int v = (i < n) ? g_deg[i] : 0;
    s[threadIdx.x] = v;
    __syncthreads();
    for (int off = 1; off < SCAN_T; off <<= 1) {
        int t = (threadIdx.x >= off) ? s[threadIdx.x - off] : 0;
        __syncthreads();
        s[threadIdx.x] += t;
        __syncthreads();
    }
    if (i < n) excl[i] = s[threadIdx.x] - v;
    if (threadIdx.x == SCAN_T - 1) g_bsum[blockIdx.x] = s[SCAN_T - 1];
}

__global__ void scan2_kernel(int nb) {
    __shared__ int s[128];
    int v = (threadIdx.x < nb) ? g_bsum[threadIdx.x] : 0;
    s[threadIdx.x] = v;
    __syncthreads();
    for (int off = 1; off < 128; off <<= 1) {
        int t = (threadIdx.x >= off) ? s[threadIdx.x - off] : 0;
        __syncthreads();
        s[threadIdx.x] += t;
        __syncthreads();
    }
    if (threadIdx.x < nb) g_bsum[threadIdx.x] = s[threadIdx.x] - v;  // exclusive
}

__global__ void scan3_kernel(int n, int E) {
    int i = blockIdx.x * blockDim.x + threadIdx.x;
    if (i < n) {
        int r = g_rowptr[i] + g_bsum[i / SCAN_T];
        g_rowptr[i] = r;
        g_pos[i] = r;
    }
    if (i == 0) g_rowptr[n] = E;
}

__global__ void scatter_kernel(const int* __restrict__ src,
                               const int* __restrict__ dst, int E) {
    int i = blockIdx.x * blockDim.x + threadIdx.x;
    if (i < E) {
        int t = dst[i];
        int slot = atomicAdd(&g_pos[t], 1);
        g_csr[slot] = src[i];
    }
}

// ---------------- pull-style mean aggregation (input-side, width d) ----------------
__global__ __launch_bounds__(HMAX)
void agg_csr_kernel(const float* __restrict__ h, float* __restrict__ hN, int d) {
    int node = blockIdx.x;
    int tid = threadIdx.x;
    int start = g_rowptr[node];
    int end   = g_rowptr[node + 1];
    __shared__ int sidx[128];
    float acc = 0.f;
    for (int base = start; base < end; base += 128) {
        int n = min(128, end - base);
        if (tid < n) sidx[tid] = g_csr[base + tid];
        __syncthreads();
        int j = 0;
        for (; j + 4 <= n; j += 4) {
            const float* r0 = h + (size_t)sidx[j + 0] * d;
            const float* r1 = h + (size_t)sidx[j + 1] * d;
            const float* r2 = h + (size_t)sidx[j + 2] * d;
            const float* r3 = h + (size_t)sidx[j + 3] * d;
            acc += r0[tid];
            acc += r1[tid];
            acc += r2[tid];
            acc += r3[tid];
        }
        for (; j < n; j++) acc += h[(size_t)g_csr[base + j] * d + tid];
        __syncthreads();
    }
    hN[(size_t)node * d + tid] = acc * g_invd[node];
}

// -------- output-side aggregation for layer 3: out[node] += mean(z[nbrs]), width 64 --------
__global__ __launch_bounds__(64)
void agg_add64_kernel(const float* __restrict__ z, float* __restrict__ out) {
    int node = blockIdx.x;
    int tid = threadIdx.x;
    int start = g_rowptr[node];
    int end   = g_rowptr[node + 1];
    __shared__ int sidx[64];
    float acc = 0.f;
    for (int base = start; base < end; base += 64) {
        int n = min(64, end - base);
        if (tid < n) sidx[tid] = g_csr[base + tid];
        __syncthreads();
        int j = 0;
        for (; j + 4 <= n; j += 4) {
            const float* r0 = z + (size_t)sidx[j + 0] * 64;
            const float* r1 = z + (size_t)sidx[j + 1] * 64;
            const float* r2 = z + (size_t)sidx[j + 2] * 64;
            const float* r3 = z + (size_t)sidx[j + 3] * 64;
            acc += r0[tid];
            acc += r1[tid];
            acc += r2[tid];
            acc += r3[tid];
        }
        for (; j < n; j++) acc += z[(size_t)sidx[j] * 64 + tid];
        __syncthreads();
    }
    out[(size_t)node * 64 + tid] += acc * g_invd[node];
}

// ================= bf16x2-split WMMA GEMM (HMMA, no 'a' features) =================
// Split: v = hi + lo (bf16 each);  D += Ahi*Bhi + Ahi*Blo + Alo*Bhi (fp32 accum).
// CTA: BM=128 x BN, BK=32. 512 threads = 16 warps (4x4), warp tile 32 x BN/4.

__device__ __forceinline__ void split_store8(__nv_bfloat16* __restrict__ hi,
                                             __nv_bfloat16* __restrict__ lo,
                                             float4 v0, float4 v1) {
    float f[8] = {v0.x, v0.y, v0.z, v0.w, v1.x, v1.y, v1.z, v1.w};
    #pragma unroll
    for (int i = 0; i < 8; i++) {
        __nv_bfloat16 h = __float2bfloat16_rn(f[i]);
        __nv_bfloat16 l = __float2bfloat16_rn(f[i] - __bfloat162float(h));
        hi[i] = h;
        lo[i] = l;
    }
}

template <int BN>
__global__ __launch_bounds__(512)
void gemm_wmma_kernel(const float* __restrict__ A0,
                      const float* __restrict__ A1,
                      const float* __restrict__ W,
                      const float* __restrict__ bias,
                      float* __restrict__ out,
                      int M, int d, int Nout, int relu) {
    constexpr int BM  = 128;
    constexpr int BK  = 32;
    constexpr int LDT = 40;           // bf16 tile stride (pad; 80B, 16B-aligned frags)
    constexpr int WN  = BN / 4;       // warp N tile: 32 or 16
    constexpr int FN  = WN / 16;      // 2 or 1
    constexpr int LDC = BN + 4;       // f32 epilogue stride

    extern __shared__ char smraw[];
    __nv_bfloat16* aHi = (__nv_bfloat16*)smraw;
    __nv_bfloat16* aLo = aHi + BM * LDT;
    __nv_bfloat16* bHi = aLo + BM * LDT;
    __nv_bfloat16* bLo = bHi + BN * LDT;
    float* Cs = (float*)smraw;        // epilogue reuse (after sync)

    const int tid = threadIdx.x;
    const int wid = tid >> 5;
    const int m0 = (wid >> 2) * 32;
    const int n0 = (wid & 3) * WN;
    const int bm = blockIdx.x * BM;
    const int bn = blockIdx.y * BN;
    const int K = 2 * d;
    const int nsteps = K / BK;

    wmma::fragment<wmma::accumulator, 16, 16, 16, float> acc[2][FN];
    #pragma unroll
    for (int fm = 0; fm < 2; fm++)
        #pragma unroll
        for (int fn = 0; fn < FN; fn++)
            wmma::fill_fragment(acc[fm][fn], 0.f);

    // staging geometry
    const int ar = tid >> 2;                 // A: 128 rows, 4 thr/row, 8 cols
    const int ac = (tid & 3) * 8;
    const int br = (BN == 128) ? (tid >> 2) : (tid >> 3);
    const int bc = (BN == 128) ? (tid & 3) * 8 : (tid & 7) * 4;
    constexpr int NB4 = (BN == 128) ? 2 : 1; // B float4s per thread

    float4 ra[2], rb[2];

    auto loadA = [&](int k0) {
        int gm = bm + ar;
        if (gm < M) {
            const float* p = (k0 < d) ? (A0 + (size_t)gm * d + k0 + ac)
                                      : (A1 + (size_t)gm * d + (k0 - d) + ac);
            ra[0] = *(const float4*)(p);
            ra[1] = *(const float4*)(p + 4);
        } else {
            ra[0] = ra[1] = make_float4(0.f, 0.f, 0.f, 0.f);
        }
    };
    auto loadB = [&](int k0) {
        const float* p = W + (size_t)(bn + br) * K + k0 + bc;
        rb[0] = *(const float4*)(p);
        if (NB4 == 2) rb[1] = *(const float4*)(p + 4);
    };

    loadA(0);
    loadB(0);

    for (int s = 0; s < nsteps; s++) {
        __syncthreads();  // previous compute done before smem overwrite
        split_store8(aHi + ar * LDT + ac, aLo + ar * LDT + ac, ra[0], ra[1]);
        if (NB4 == 2) {
            split_store8(bHi + br * LDT + bc, bLo + br * LDT + bc, rb[0], rb[1]);
        } else {
            float f[4] = {rb[0].x, rb[0].y, rb[0].z, rb[0].w};
            #pragma unroll
            for (int i = 0; i < 4; i++) {
                __nv_bfloat16 h = __float2bfloat16_rn(f[i]);
                __nv_bfloat16 l = __float2bfloat16_rn(f[i] - __bfloat162float(h));
                bHi[br * LDT + bc + i] = h;
                bLo[br * LDT + bc + i] = l;
            }
        }
        __syncthreads();

        if (s + 1 < nsteps) {  // prefetch next step; overlaps HMMA below
            loadA((s + 1) * BK);
            loadB((s + 1) * BK);
        }

        #pragma unroll
        for (int ks = 0; ks < BK; ks += 16) {
            wmma::fragment<wmma::matrix_a, 16, 16, 16, __nv_bfloat16, wmma::row_major> a_hi[2], a_lo[2];
            #pragma unroll
            for (int fm = 0; fm < 2; fm++) {
                wmma::load_matrix_sync(a_hi[fm], aHi + (m0 + fm * 16) * LDT + ks, LDT);
                wmma::load_matrix_sync(a_lo[fm], aLo + (m0 + fm * 16) * LDT + ks, LDT);
            }
            #pragma unroll
            for (int fn = 0; fn < FN; fn++) {
                wmma::fragment<wmma::matrix_b, 16, 16, 16, __nv_bfloat16, wmma::col_major> b_hi, b_lo;
                wmma::load_matrix_sync(b_hi, bHi + (n0 + fn * 16) * LDT + ks, LDT);
                wmma::load_matrix_sync(b_lo, bLo + (n0 + fn * 16) * LDT + ks, LDT);
                #pragma unroll
                for (int fm = 0; fm < 2; fm++) {
                    wmma::mma_sync(acc[fm][fn], a_hi[fm], b_hi, acc[fm][fn]);
                    wmma::mma_sync(acc[fm][fn], a_hi[fm], b_lo, acc[fm][fn]);
                    wmma::mma_sync(acc[fm][fn], a_lo[fm], b_hi, acc[fm][fn]);
                }
            }
        }
    }

    // ---- epilogue: frags -> smem -> bias/relu -> global ----
    __syncthreads();
    #pragma unroll
    for (int fm = 0; fm < 2; fm++)
        #pragma unroll
        for (int fn = 0; fn < FN; fn++)
            wmma::store_matrix_sync(Cs + (m0 + fm * 16) * LDC + n0 + fn * 16,
                                    acc[fm][fn], LDC, wmma::mem_row_major);
    __syncthreads();

    {
        constexpr int CPT = (BM * BN) / 512;     // floats per thread: 32 or 16
        constexpr int NF4 = CPT / 4;             // 8 or 4
        const int row = tid >> 2;
        const int c0 = (tid & 3) * CPT;
        const int gm = bm + row;
        if (gm < M) {
            #pragma unroll
            for (int j = 0; j < NF4; j++) {
                int c = c0 + j * 4;
                float4 v = *(const float4*)(Cs + row * LDC + c);
                v.x += bias[bn + c + 0];
                v.y += bias[bn + c + 1];
                v.z += bias[bn + c + 2];
                v.w += bias[bn + c + 3];
                if (relu) {
                    v.x = fmaxf(v.x, 0.f); v.y = fmaxf(v.y, 0.f);
                    v.z = fmaxf(v.z, 0.f); v.w = fmaxf(v.w, 0.f);
                }
                *(float4*)(out + (size_t)gm * Nout + bn + c) = v;
            }
        }
    }
}

// -------- Layer-3 fused GEMM: BN=128 over stacked [W3self ; W3neigh] (64 rows each) --------
// A = h2 (single, K=256). cols 0..63 -> out (+bias3). cols 64..127 -> z (raw).
__global__ __launch_bounds__(512)
void gemm_wmma_l3_kernel(const float* __restrict__ A,
                         const float* __restrict__ W3,    // [64 x 512]
                         const float* __restrict__ bias,
                         float* __restrict__ out,         // [M x 64]
                         float* __restrict__ z,           // [M x 64]
                         int M) {
    constexpr int BM  = 128;
    constexpr int BN  = 128;
    constexpr int BK  = 32;
    constexpr int LDT = 40;
    constexpr int WN  = 32;
    constexpr int FN  = 2;
    constexpr int LDC = BN + 4;
    constexpr int Kc  = 256;

    extern __shared__ char smraw[];
    __nv_bfloat16* aHi = (__nv_bfloat16*)smraw;
    __nv_bfloat16* aLo = aHi + BM * LDT;
    __nv_bfloat16* bHi = aLo + BM * LDT;
    __nv_bfloat16* bLo = bHi + BN * LDT;
    float* Cs = (float*)smraw;

    const int tid = threadIdx.x;
    const int wid = tid >> 5;
    const int m0 = (wid >> 2) * 32;
    const int n0 = (wid & 3) * WN;
    const int bm = blockIdx.x * BM;
    const int nsteps = Kc / BK;   // 8

    wmma::fragment<wmma::accumulator, 16, 16, 16, float> acc[2][FN];
    #pragma unroll
    for (int fm = 0; fm < 2; fm++)
        #pragma unroll
        for (int fn = 0; fn < FN; fn++)
            wmma::fill_fragment(acc[fm][fn], 0.f);

    const int ar = tid >> 2;
    const int ac = (tid & 3) * 8;
    const int br = tid >> 2;       // virtual row 0..127
    const int bc = (tid & 3) * 8;
    const int wrow = br & 63;      // W3 row
    const int woff = (br >> 6) * 256;  // 0 = self half, 256 = neighbor half

    float4 ra[2], rb[2];

    auto loadA = [&](int k0) {
        int gm = bm + ar;
        if (gm < M) {
            const float* p = A + (size_t)gm * Kc + k0 + ac;
            ra[0] = *(const float4*)(p);
            ra[1] = *(const float4*)(p + 4);
        } else {
            ra[0] = ra[1] = make_float4(0.f, 0.f, 0.f, 0.f);
        }
    };
    auto loadB = [&](int k0) {
        const float* p = W3 + (size_t)wrow * 512 + woff + k0 + bc;
        rb[0] = *(const float4*)(p);
        rb[1] = *(const float4*)(p + 4);
    };

    loadA(0);
    loadB(0);

    for (int s = 0; s < nsteps; s++) {
        __syncthreads();
        split_store8(aHi + ar * LDT + ac, aLo + ar * LDT + ac, ra[0], ra[1]);
        split_store8(bHi + br * LDT + bc, bLo + br * LDT + bc, rb[0], rb[1]);
        __syncthreads();

        if (s + 1 < nsteps) {
            loadA((s + 1) * BK);
            loadB((s + 1) * BK);
        }

        #pragma unroll
        for (int ks = 0; ks < BK; ks += 16) {
            wmma::fragment<wmma::matrix_a, 16, 16, 16, __nv_bfloat16, wmma::row_major> a_hi[2], a_lo[2];
            #pragma unroll
            for (int fm = 0; fm < 2; fm++) {
                wmma::load_matrix_sync(a_hi[fm], aHi + (m0 + fm * 16) * LDT + ks, LDT);
                wmma::load_matrix_sync(a_lo[fm], aLo + (m0 + fm * 16) * LDT + ks, LDT);
            }
            #pragma unroll
            for (int fn = 0; fn < FN; fn++) {
                wmma::fragment<wmma::matrix_b, 16, 16, 16, __nv_bfloat16, wmma::col_major> b_hi, b_lo;
                wmma::load_matrix_sync(b_hi, bHi + (n0 + fn * 16) * LDT + ks, LDT);
                wmma::load_matrix_sync(b_lo, bLo + (n0 + fn * 16) * LDT + ks, LDT);
                #pragma unroll
                for (int fm = 0; fm < 2; fm++) {
                    wmma::mma_sync(acc[fm][fn], a_hi[fm], b_hi, acc[fm][fn]);
                    wmma::mma_sync(acc[fm][fn], a_hi[fm], b_lo, acc[fm][fn]);
                    wmma::mma_sync(acc[fm][fn], a_lo[fm], b_hi, acc[fm][fn]);
                }
            }
        }
    }

    __syncthreads();
    #pragma unroll
    for (int fm = 0; fm < 2; fm++)
        #pragma unroll
        for (int fn = 0; fn < FN; fn++)
            wmma::store_matrix_sync(Cs + (m0 + fm * 16) * LDC + n0 + fn * 16,
                                    acc[fm][fn], LDC, wmma::mem_row_major);
    __syncthreads();

    {
        // 32 floats per thread: row = tid>>2, c0 = (tid&3)*32 -> chunk fully in
        // one region (c0 in {0,32}: self -> out; {64,96}: neighbor -> z).
        const int row = tid >> 2;
        const int c0 = (tid & 3) * 32;
        const int gm = bm + row;
        if (gm < M) {
            if (c0 < 64) {
                #pragma unroll
                for (int j = 0; j < 8; j++) {
                    int c = c0 + j * 4;
                    float4 v = *(const float4*)(Cs + row * LDC + c);
                    v.x += bias[c + 0];
                    v.y += bias[c + 1];
                    v.z += bias[c + 2];
                    v.w += bias[c + 3];
                    *(float4*)(out + (size_t)gm * 64 + c) = v;
                }
            } else {
                #pragma unroll
                for (int j = 0; j < 8; j++) {
                    int c = c0 + j * 4;
                    float4 v = *(const float4*)(Cs + row * LDC + c);
                    *(float4*)(z + (size_t)gm * 64 + (c - 64)) = v;
                }
            }
        }
    }
}

extern "C" void kernel_launch(void* const* d_in, const int* in_sizes, int n_in,
                              void* d_out, int out_size) {
    const float* x   = (const float*)d_in[0];
    const int*   src = (const int*)d_in[1];
    const int*   dst = (const int*)d_in[2];
    const float* W1 = (const float*)d_in[3];
    const float* b1 = (const float*)d_in[4];
    const float* W2 = (const float*)d_in[5];
    const float* b2 = (const float*)d_in[6];
    const float* W3 = (const float*)d_in[7];
    const float* b3 = (const float*)d_in[8];
    float* out = (float*)d_out;

    const int E = in_sizes[1];
    const int M = in_sizes[0] / IN_FEATS;   // 100000

    float *h1, *h2, *hN;
    int *deg, *rowptr;
    cudaGetSymbolAddress((void**)&h1,     g_h1);
    cudaGetSymbolAddress((void**)&h2,     g_h2);
    cudaGetSymbolAddress((void**)&hN,     g_hN);
    cudaGetSymbolAddress((void**)&deg,    g_deg);
    cudaGetSymbolAddress((void**)&rowptr, g_rowptr);

    // dynamic smem: max(tiles, epilogue Cs)
    const int SMEM128 = 128 * 132 * 4;  // 67584
    cudaFuncSetAttribute(gemm_wmma_kernel<128>,
                         cudaFuncAttributeMaxDynamicSharedMemorySize, SMEM128);
    cudaFuncSetAttribute(gemm_wmma_l3_kernel,
                         cudaFuncAttributeMaxDynamicSharedMemorySize, SMEM128);

    const int T = 256;
    const int gx = (M + 127) / 128;

    // degrees + CSR build (recomputed every call: deterministic work)
    zero_int_kernel<<<(M + T - 1) / T, T>>>(deg, M);
    deg_kernel<<<(E + T - 1) / T, T>>>(dst, E);
    invd_kernel<<<(M + T - 1) / T, T>>>(M);

    int nb = (M + SCAN_T - 1) / SCAN_T;
    scan1_kernel<<<nb, SCAN_T>>>(rowptr, M);
    scan2_kernel<<<1, 128>>>(nb);
    scan3_kernel<<<(M + T - 1) / T, T>>>(M, E);
    scatter_kernel<<<(E + T - 1) / T, T>>>(src, dst, E);

    // ---- Layer 1: d=128, Nout=256, relu (input-side aggregation) ----
    agg_csr_kernel<<<M, IN_FEATS>>>(x, hN, IN_FEATS);
    gemm_wmma_kernel<128><<<dim3(gx, 2), 512, SMEM128>>>(x, hN, W1, b1, h1, M, IN_FEATS, 256, 1);

    // ---- Layer 2: d=256, Nout=256, relu (input-side aggregation) ----
    agg_csr_kernel<<<M, 256>>>(h1, hN, 256);
    gemm_wmma_kernel<128><<<dim3(gx, 2), 512, SMEM128>>>(h1, hN, W2, b2, h2, M, 256, 256, 1);

    // ---- Layer 3: d=256, Nout=64 (OUTPUT-side aggregation, width 64) ----
    // One GEMM computes self part (-> out, +bias) and pre-aggregation neighbor
    // part z = h2 @ W3neigh^T (-> hN scratch); then out += mean(z[nbrs]).
    gemm_wmma_l3_kernel<<<gx, 512, SMEM128>>>(h2, W3, b3, out, hN, M);
    agg_add64_kernel<<<M, 64>>>(hN, out);
}